// round 16
// baseline (speedup 1.0000x reference)
#include <cuda_runtime.h>
#include <cuda_fp16.h>
#include <cstdint>
#include <math.h>

#define NUM_TOKENS 8192
#define HIDDEN 4096
#define NUM_EXPERTS 8
#define INTER 2048

// ---------------- device scratch (no allocs allowed) ----------------
__device__ int    g_cnt[NUM_EXPERTS];
__device__ int    g_idx[NUM_EXPERTS * NUM_TOKENS];
__device__ __half g_xh[(size_t)NUM_TOKENS * HIDDEN];                  // 67 MB
__device__ __half g_w1h[(size_t)NUM_EXPERTS * HIDDEN * 2 * INTER];    // 268 MB, [e][H][2I] (native)
__device__ __half g_w2h[(size_t)NUM_EXPERTS * INTER * HIDDEN];        // 134 MB, [e][I][H]  (native)
__device__ __half g_interh[(size_t)NUM_TOKENS * INTER];               // 33 MB

// ---------------- routing ----------------
__global__ void zero_cnt_kernel() {
    if (threadIdx.x < NUM_EXPERTS) g_cnt[threadIdx.x] = 0;
}

__global__ void route_kernel(const int* __restrict__ tok32) {
    __shared__ int s_is32;
    if (threadIdx.x == 0) {
        int any = 0;
        #pragma unroll
        for (int j = 1; j < 32; j += 2) any |= tok32[j];
        s_is32 = (any != 0);
    }
    __syncthreads();
    int i = blockIdx.x * blockDim.x + threadIdx.x;
    if (i < NUM_TOKENS) {
        int e;
        if (s_is32) e = tok32[i] & 7;
        else {
            long long t = ((const long long*)tok32)[i];
            e = (int)(t & 7);
        }
        int slot = atomicAdd(&g_cnt[e], 1);
        g_idx[e * NUM_TOKENS + slot] = i;
    }
}

// ---------------- preprocessing: streaming fp32 -> fp16 ----------------
__device__ __forceinline__ void cvt8(const float4* __restrict__ in, __half* __restrict__ out, size_t idx) {
    float4 v0 = in[idx * 2];
    float4 v1 = in[idx * 2 + 1];
    __half2 h0 = __floats2half2_rn(v0.x, v0.y);
    __half2 h1 = __floats2half2_rn(v0.z, v0.w);
    __half2 h2 = __floats2half2_rn(v1.x, v1.y);
    __half2 h3 = __floats2half2_rn(v1.z, v1.w);
    uint4 u;
    u.x = *(uint32_t*)&h0; u.y = *(uint32_t*)&h1;
    u.z = *(uint32_t*)&h2; u.w = *(uint32_t*)&h3;
    *(uint4*)&out[idx * 8] = u;
}

// x (4.19M chunks) + w1 (16.78M chunks) in one bandwidth-bound kernel.
__global__ void convert_xw1_kernel(const float4* __restrict__ x4, const float4* __restrict__ w4) {
    size_t i = (size_t)blockIdx.x * blockDim.x + threadIdx.x;   // 4194304 threads
    cvt8(x4, g_xh, i);
    #pragma unroll
    for (int t = 0; t < 4; t++)
        cvt8(w4, g_w1h, i + (size_t)t * 4194304);
}

// ---------------- helpers ----------------
__device__ __forceinline__ void cp16(uint32_t dst, const void* src, bool pred) {
    int sz = pred ? 16 : 0;
    asm volatile("cp.async.cg.shared.global [%0], [%1], 16, %2;\n"
                 :: "r"(dst), "l"(src), "r"(sz));
}
__device__ __forceinline__ void cp_commit() { asm volatile("cp.async.commit_group;\n"); }
__device__ __forceinline__ void cp_wait2()  { asm volatile("cp.async.wait_group 2;\n"); }

__device__ __forceinline__ void mma_fp16(float& c0, float& c1, float& c2, float& c3,
                                         uint32_t a0, uint32_t a1, uint32_t a2, uint32_t a3,
                                         uint32_t b0, uint32_t b1) {
    asm volatile("mma.sync.aligned.m16n8k16.row.col.f32.f16.f16.f32 "
                 "{%0,%1,%2,%3}, {%4,%5,%6,%7}, {%8,%9}, {%0,%1,%2,%3};\n"
                 : "+f"(c0), "+f"(c1), "+f"(c2), "+f"(c3)
                 : "r"(a0), "r"(a1), "r"(a2), "r"(a3), "r"(b0), "r"(b1));
}

#define LDSM4(r0, r1, r2, r3, addr) \
    asm volatile("ldmatrix.sync.aligned.m8n8.x4.shared.b16 {%0,%1,%2,%3}, [%4];" \
                 : "=r"(r0), "=r"(r1), "=r"(r2), "=r"(r3) : "r"(addr))
#define LDSM4T(r0, r1, r2, r3, addr) \
    asm volatile("ldmatrix.sync.aligned.m8n8.x4.trans.shared.b16 {%0,%1,%2,%3}, [%4];" \
                 : "=r"(r0), "=r"(r1), "=r"(r2), "=r"(r3) : "r"(addr))

// ---------------- smem geometry ----------------
// BK = 32. A tile: 128 rows x 32 halves, stride 40 (80 B = 16*5, ldmatrix-aligned,
// conflict-free: 20-bank row steps). B tiles: [K=32 rows][N cols], k-major.
#define AST    40
#define ATILE  (128 * AST)            // 5120 halves
// gemm1: Bg + Bu, each 32 x 72 (N=64 + 8 pad; 144 B rows)
#define BST1   72
#define BG1    ATILE
#define BU1    (ATILE + 32 * BST1)
#define STAGE1 (ATILE + 2 * 32 * BST1)  // 9728 halves = 19456 B
// gemm2: B 32 x 136 (N=128 + 8 pad; 272 B rows)
#define BST2   136
#define BOFF2  ATILE
#define STAGE2 (ATILE + 32 * BST2)    // 9472 halves = 18944 B
#define NSTAGE 4
#define G1_SMEM (NSTAGE * STAGE1 * 2 + 512)   // ~78.3 KB
#define G2_SMEM (NSTAGE * STAGE2 * 2 + 512)   // ~76.3 KB

// ======================================================================
// GEMM1 (+fused w2 convert at z=0): gu = Xh_gathered @ W1h[e] (K=4096, BK=32),
// silu*up -> g_interh. Tile: M=128, gate N=64 + up N=64.
// z=0: w2 fp32->fp16 convert slice (runs first, overlaps with GEMM blocks).
// z=1..8: expert e = z-1.
// ======================================================================
__global__ __launch_bounds__(256, 2) void gemm1_kernel(const float4* __restrict__ w2f) {
    if (blockIdx.z == 0) {
        // 32*64 = 2048 blocks x 256 thr = 524288 threads; 8388608 chunks total.
        size_t base = (size_t)(blockIdx.y * 32 + blockIdx.x) * 256 + threadIdx.x;
        #pragma unroll
        for (int t = 0; t < 16; t++)
            cvt8(w2f, g_w2h, base + (size_t)t * 524288);
        return;
    }

    extern __shared__ __half smh[];
    int* ridx = (int*)(smh + NSTAGE * STAGE1);

    const int e   = blockIdx.z - 1;
    const int cnt = g_cnt[e];
    const int m0  = blockIdx.y * 128;
    if (m0 >= cnt) return;
    const int n0  = blockIdx.x * 64;

    const int tid = threadIdx.x;
    if (tid < 128) {
        int m = m0 + tid;
        ridx[tid] = (m < cnt) ? g_idx[e * NUM_TOKENS + m] : -1;
    }
    __syncthreads();

    const __half* W = g_w1h + (size_t)e * HIDDEN * (2 * INTER);

    const int wid = tid >> 5, lane = tid & 31;
    const int warp_m = wid & 1, warp_n = wid >> 1;
    const int gid = lane >> 2, tig = lane & 3;

    float cg[4][2][4], cu[4][2][4];
    #pragma unroll
    for (int a = 0; a < 4; a++)
        #pragma unroll
        for (int b = 0; b < 2; b++)
            #pragma unroll
            for (int c = 0; c < 4; c++) { cg[a][b][c] = 0.f; cu[a][b][c] = 0.f; }

    // A loads: 128 rows x 4 chunks(8h) = 512 vec -> 2/thread
    const __half* asrc[2]; bool apred[2]; uint32_t adst[2];
    #pragma unroll
    for (int t = 0; t < 2; t++) {
        int vec = tid + t * 256;
        int arow = vec >> 2, acv = vec & 3;
        int r = ridx[arow];
        apred[t] = (r >= 0);
        asrc[t] = g_xh + (size_t)(apred[t] ? r : 0) * HIDDEN + acv * 8;
        adst[t] = (arow * AST + acv * 8) * 2;
    }
    // B loads: 32 k-rows x 8 chunks each for gate & up -> 1+1 per thread
    const int brow = tid >> 3, bcv = tid & 7;
    const __half* bsrc_g = W + (size_t)brow * (2 * INTER) + n0 + bcv * 8;
    const __half* bsrc_u = bsrc_g + INTER;
    const uint32_t bdst_g = (BG1 + brow * BST1 + bcv * 8) * 2;
    const uint32_t bdst_u = (BU1 + brow * BST1 + bcv * 8) * 2;

    uint32_t sb = (uint32_t)__cvta_generic_to_shared(smh);

    auto prefetch = [&](int kt) {
        int buf = kt & (NSTAGE - 1);
        int k0 = kt * 32;
        uint32_t sbb = sb + buf * STAGE1 * 2;
        #pragma unroll
        for (int t = 0; t < 2; t++) cp16(sbb + adst[t], asrc[t] + k0, apred[t]);
        size_t wko = (size_t)k0 * (2 * INTER);
        cp16(sbb + bdst_g, bsrc_g + wko, true);
        cp16(sbb + bdst_u, bsrc_u + wko, true);
    };

    // ldmatrix offsets (bytes)
    const uint32_t aoff = ((warp_m * 64 + (lane & 15)) * AST + (lane >> 4) * 8) * 2;
    const uint32_t brow_l = (lane & 7) + ((lane >> 3) & 1) * 8;     // k row within 16
    const uint32_t boff = (brow_l * BST1 + warp_n * 16 + (lane >> 4) * 8) * 2;

    auto compute = [&](int buf) {
        uint32_t abase = sb + buf * STAGE1 * 2 + aoff;
        uint32_t gbase = sb + (buf * STAGE1 + BG1) * 2 + boff;
        uint32_t ubase = sb + (buf * STAGE1 + BU1) * 2 + boff;
        #pragma unroll
        for (int ks = 0; ks < 2; ks++) {
            uint32_t ka = ks * 16 * 2;              // k halves within A row
            uint32_t kb = ks * 16 * BST1 * 2;       // k rows within B tile
            uint32_t a[4][4];
            #pragma unroll
            for (int mt = 0; mt < 4; mt++)
                LDSM4(a[mt][0], a[mt][1], a[mt][2], a[mt][3],
                      abase + mt * 16 * AST * 2 + ka);
            uint32_t bg[2][2], bu[2][2];
            LDSM4T(bg[0][0], bg[0][1], bg[1][0], bg[1][1], gbase + kb);
            LDSM4T(bu[0][0], bu[0][1], bu[1][0], bu[1][1], ubase + kb);
            #pragma unroll
            for (int mt = 0; mt < 4; mt++)
                #pragma unroll
                for (int nt = 0; nt < 2; nt++) {
                    mma_fp16(cg[mt][nt][0], cg[mt][nt][1], cg[mt][nt][2], cg[mt][nt][3],
                             a[mt][0], a[mt][1], a[mt][2], a[mt][3], bg[nt][0], bg[nt][1]);
                    mma_fp16(cu[mt][nt][0], cu[mt][nt][1], cu[mt][nt][2], cu[mt][nt][3],
                             a[mt][0], a[mt][1], a[mt][2], a[mt][3], bu[nt][0], bu[nt][1]);
                }
        }
    };

    const int NK = HIDDEN / 32;   // 128
    prefetch(0); cp_commit();
    prefetch(1); cp_commit();
    prefetch(2); cp_commit();
    for (int kt = 0; kt < NK; kt++) {
        cp_wait2();
        __syncthreads();
        if (kt + 3 < NK) prefetch(kt + 3);   // issue loads before compute: +1 stage of hiding
        cp_commit();
        compute(kt & (NSTAGE - 1));
    }

    // epilogue: silu(gate)*up -> g_interh (fp16)
    #pragma unroll
    for (int mt = 0; mt < 4; mt++) {
        int lm = warp_m * 64 + mt * 16 + gid;
        int t0 = ridx[lm];
        int t1 = ridx[lm + 8];
        #pragma unroll
        for (int nt = 0; nt < 2; nt++) {
            int col = n0 + warp_n * 16 + nt * 8 + 2 * tig;
            if (t0 >= 0) {
                float g0 = cg[mt][nt][0], u0 = cu[mt][nt][0];
                float g1 = cg[mt][nt][1], u1 = cu[mt][nt][1];
                float v0 = g0 / (1.f + __expf(-g0)) * u0;
                float v1 = g1 / (1.f + __expf(-g1)) * u1;
                *(__half2*)&g_interh[(size_t)t0 * INTER + col] = __floats2half2_rn(v0, v1);
            }
            if (t1 >= 0) {
                float g0 = cg[mt][nt][2], u0 = cu[mt][nt][2];
                float g1 = cg[mt][nt][3], u1 = cu[mt][nt][3];
                float v0 = g0 / (1.f + __expf(-g0)) * u0;
                float v1 = g1 / (1.f + __expf(-g1)) * u1;
                *(__half2*)&g_interh[(size_t)t1 * INTER + col] = __floats2half2_rn(v0, v1);
            }
        }
    }
}

// ======================================================================
// GEMM2: out = interh_gathered @ W2h[e] (K=2048, BK=32), scatter fp32 rows.
// Tile 128 x 128. 8 warps: warp_m{0,1} x warp_n{0..3} (32 cols each).
// ======================================================================
__global__ __launch_bounds__(256, 2) void gemm2_kernel(float* __restrict__ out) {
    extern __shared__ __half smh[];
    int* ridx = (int*)(smh + NSTAGE * STAGE2);

    const int e   = blockIdx.z;
    const int cnt = g_cnt[e];
    const int m0  = blockIdx.y * 128;
    if (m0 >= cnt) return;
    const int n0  = blockIdx.x * 128;

    const int tid = threadIdx.x;
    if (tid < 128) {
        int m = m0 + tid;
        ridx[tid] = (m < cnt) ? g_idx[e * NUM_TOKENS + m] : -1;
    }
    __syncthreads();

    const __half* W = g_w2h + (size_t)e * INTER * HIDDEN;

    const int wid = tid >> 5, lane = tid & 31;
    const int warp_m = wid & 1, warp_n = wid >> 1;
    const int gid = lane >> 2, tig = lane & 3;

    float cc[4][4][4];
    #pragma unroll
    for (int a = 0; a < 4; a++)
        #pragma unroll
        for (int b = 0; b < 4; b++)
            #pragma unroll
            for (int c = 0; c < 4; c++) cc[a][b][c] = 0.f;

    const __half* asrc[2]; bool apred[2]; uint32_t adst[2];
    #pragma unroll
    for (int t = 0; t < 2; t++) {
        int vec = tid + t * 256;
        int arow = vec >> 2, acv = vec & 3;
        int r = ridx[arow];
        apred[t] = (r >= 0);
        asrc[t] = g_interh + (size_t)(apred[t] ? r : 0) * INTER + acv * 8;
        adst[t] = (arow * AST + acv * 8) * 2;
    }
    // B: 32 k-rows x 16 chunks = 512 vec -> 2/thread
    const __half* bsrc[2]; uint32_t bdst[2];
    #pragma unroll
    for (int t = 0; t < 2; t++) {
        int vec = tid + t * 256;
        int brow = vec >> 4, bcv = vec & 15;
        bsrc[t] = W + (size_t)brow * HIDDEN + n0 + bcv * 8;
        bdst[t] = (BOFF2 + brow * BST2 + bcv * 8) * 2;
    }

    uint32_t sb = (uint32_t)__cvta_generic_to_shared(smh);

    auto prefetch = [&](int kt) {
        int buf = kt & (NSTAGE - 1);
        int k0 = kt * 32;
        uint32_t sbb = sb + buf * STAGE2 * 2;
        #pragma unroll
        for (int t = 0; t < 2; t++) cp16(sbb + adst[t], asrc[t] + k0, apred[t]);
        size_t wko = (size_t)k0 * HIDDEN;
        #pragma unroll
        for (int t = 0; t < 2; t++) cp16(sbb + bdst[t], bsrc[t] + wko, true);
    };

    const uint32_t aoff = ((warp_m * 64 + (lane & 15)) * AST + (lane >> 4) * 8) * 2;
    const uint32_t brow_l = (lane & 7) + ((lane >> 3) & 1) * 8;
    const uint32_t boff = (brow_l * BST2 + warp_n * 32 + (lane >> 4) * 8) * 2;

    auto compute = [&](int buf) {
        uint32_t abase = sb + buf * STAGE2 * 2 + aoff;
        uint32_t bbase = sb + (buf * STAGE2 + BOFF2) * 2 + boff;
        #pragma unroll
        for (int ks = 0; ks < 2; ks++) {
            uint32_t ka = ks * 16 * 2;
            uint32_t kb = ks * 16 * BST2 * 2;
            uint32_t a[4][4];
            #pragma unroll
            for (int mt = 0; mt < 4; mt++)
                LDSM4(a[mt][0], a[mt][1], a[mt][2], a[mt][3],
                      abase + mt * 16 * AST * 2 + ka);
            uint32_t b[4][2];
            LDSM4T(b[0][0], b[0][1], b[1][0], b[1][1], bbase + kb);
            LDSM4T(b[2][0], b[2][1], b[3][0], b[3][1], bbase + kb + 16 * 2);
            #pragma unroll
            for (int mt = 0; mt < 4; mt++)
                #pragma unroll
                for (int nt = 0; nt < 4; nt++)
                    mma_fp16(cc[mt][nt][0], cc[mt][nt][1], cc[mt][nt][2], cc[mt][nt][3],
                             a[mt][0], a[mt][1], a[mt][2], a[mt][3], b[nt][0], b[nt][1]);
        }
    };

    const int NK = INTER / 32;   // 64
    prefetch(0); cp_commit();
    prefetch(1); cp_commit();
    prefetch(2); cp_commit();
    for (int kt = 0; kt < NK; kt++) {
        cp_wait2();
        __syncthreads();
        if (kt + 3 < NK) prefetch(kt + 3);
        cp_commit();
        compute(kt & (NSTAGE - 1));
    }

    // epilogue: scatter fp32 rows to out
    #pragma unroll
    for (int mt = 0; mt < 4; mt++) {
        int lm = warp_m * 64 + mt * 16 + gid;
        int t0 = ridx[lm];
        int t1 = ridx[lm + 8];
        #pragma unroll
        for (int nt = 0; nt < 4; nt++) {
            int col = n0 + warp_n * 32 + nt * 8 + 2 * tig;
            if (t0 >= 0) {
                float2 v = make_float2(cc[mt][nt][0], cc[mt][nt][1]);
                *(float2*)&out[(size_t)t0 * HIDDEN + col] = v;
            }
            if (t1 >= 0) {
                float2 v = make_float2(cc[mt][nt][2], cc[mt][nt][3]);
                *(float2*)&out[(size_t)t1 * HIDDEN + col] = v;
            }
        }
    }
}

// ---------------- launch ----------------
extern "C" void kernel_launch(void* const* d_in, const int* in_sizes, int n_in,
                              void* d_out, int out_size) {
    const float* x  = nullptr;
    const float* w1 = nullptr;
    const float* w2 = nullptr;
    const int*   tok = nullptr;
    for (int i = 0; i < n_in; i++) {
        long long n = in_sizes[i];
        if (n == (long long)NUM_TOKENS) tok = (const int*)d_in[i];
        else if (n == (long long)NUM_TOKENS * HIDDEN) x = (const float*)d_in[i];
        else if (n == (long long)NUM_EXPERTS * HIDDEN * 2 * INTER) w1 = (const float*)d_in[i];
        else if (n == (long long)NUM_EXPERTS * INTER * HIDDEN) w2 = (const float*)d_in[i];
    }
    float* out = (float*)d_out;

    cudaFuncSetAttribute(gemm1_kernel, cudaFuncAttributeMaxDynamicSharedMemorySize, G1_SMEM);
    cudaFuncSetAttribute(gemm2_kernel, cudaFuncAttributeMaxDynamicSharedMemorySize, G2_SMEM);

    zero_cnt_kernel<<<1, 32>>>();
    route_kernel<<<NUM_TOKENS / 256, 256>>>(tok);

    // preprocessing: x + w1 converted up front; w2 converted inside gemm1 (z=0 slice)
    convert_xw1_kernel<<<16384, 256>>>((const float4*)x, (const float4*)w1);

    // gemm1: n-tiles (32) x m-tiles (64) x (1 convert slice + 8 experts)
    gemm1_kernel<<<dim3(32, 64, 9), 256, G1_SMEM>>>((const float4*)w2);
    // gemm2: n-tiles (4096/128=32) x m-tiles (64) x experts (8)
    gemm2_kernel<<<dim3(32, 64, 8), 256, G2_SMEM>>>(out);
}